// round 9
// baseline (speedup 1.0000x reference)
#include <cuda_runtime.h>
#include <math.h>

#define N_NODES  50000
#define N_EDGES  800000
#define N_GRAPHS 50
#define D        128
#define D_OUT    10

#define SCAN_B   1024
#define RCHUNK   256

#define TM  64             // fused-layer row tile
#define AST 66             // padded Asm row stride (even -> 8B-aligned pairs)

// ---------------- scratch (device globals: allocation-free) ----------------
__device__ int   g_indeg[N_NODES];
__device__ int   g_outdeg[N_NODES];
__device__ float g_nsrc[N_NODES];
__device__ float g_ndst[N_NODES];
__device__ int   g_rowstart[N_NODES];
__device__ int   g_cursor[N_NODES];
__device__ int2  g_edge[N_EDGES];        // (src_col, bitcast(norm_src))
__device__ int   g_incl[64];             // inclusive block prefix
__device__ int   g_flag[64];             // publish flags for chained scan
__device__ int   g_ticket;               // readout last-block ticket
__device__ float g_xa [N_NODES * D];
__device__ float g_xb [N_NODES * D];
__device__ float g_hg [N_GRAPHS * D];
__device__ int   g_cnt[N_GRAPHS];

// ---------------- packed f32x2 helpers (sm_100+) ----------------
__device__ __forceinline__ unsigned long long pack2(float lo, float hi) {
    unsigned long long r;
    asm("mov.b64 %0, {%1, %2};" : "=l"(r) : "f"(lo), "f"(hi));
    return r;
}
__device__ __forceinline__ void unpack2(unsigned long long v, float &lo, float &hi) {
    asm("mov.b64 {%0, %1}, %2;" : "=f"(lo), "=f"(hi) : "l"(v));
}
__device__ __forceinline__ void fma2(unsigned long long &acc,
                                     unsigned long long a, unsigned long long b) {
    asm("fma.rn.f32x2 %0, %1, %2, %0;" : "+l"(acc) : "l"(a), "l"(b));
}

// ---------------- setup kernels ----------------
__global__ void k_init() {
    int i = blockIdx.x * blockDim.x + threadIdx.x;
    if (i < N_NODES) { g_indeg[i] = 0; g_outdeg[i] = 0; }
    if (i < 64) { g_flag[i] = 0; }
    if (i == 0) g_ticket = 0;
}

__global__ void k_deg(const int* __restrict__ src, const int* __restrict__ dst) {
    int e = blockIdx.x * blockDim.x + threadIdx.x;
    if (e < N_EDGES) {
        atomicAdd(&g_outdeg[src[e]], 1);
        atomicAdd(&g_indeg[dst[e]], 1);
    }
}

// single-pass scan: local Hillis-Steele + sequential block chaining,
// then finalize (rowstart/cursor/norms) + zero readout accumulators. All
// 49 blocks are resident simultaneously (148 SMs) so the spin is safe.
__global__ void kscan() {
    __shared__ int sm[SCAN_B];
    __shared__ int sprev;
    int b   = blockIdx.x;
    int tid = threadIdx.x;
    int i   = b * SCAN_B + tid;
    int v = (i < N_NODES) ? g_indeg[i] : 0;
    sm[tid] = v;
    __syncthreads();
    for (int off = 1; off < SCAN_B; off <<= 1) {
        int t = (tid >= off) ? sm[tid - off] : 0;
        __syncthreads();
        sm[tid] += t;
        __syncthreads();
    }
    if (tid == 0) {
        int total = sm[SCAN_B - 1];
        int prev = 0;
        if (b > 0) {
            while (((volatile int*)g_flag)[b - 1] == 0) { }
            __threadfence();
            prev = g_incl[b - 1];
        }
        g_incl[b] = prev + total;
        __threadfence();
        ((volatile int*)g_flag)[b] = 1;
        sprev = prev;
    }
    __syncthreads();
    int base = sprev;
    if (i < N_NODES) {
        int rs = sm[tid] - v + base;        // exclusive global prefix
        g_rowstart[i] = rs;
        g_cursor[i]   = rs;
        g_nsrc[i] = rsqrtf((float)max(g_outdeg[i], 1));
        g_ndst[i] = rsqrtf((float)max(g_indeg[i], 1));
    }
    if (i < N_GRAPHS * D) g_hg[i] = 0.0f;
    if (i < N_GRAPHS) g_cnt[i] = 0;
}

__global__ void k_fill(const int* __restrict__ src, const int* __restrict__ dst) {
    int e = blockIdx.x * blockDim.x + threadIdx.x;
    if (e < N_EDGES) {
        int d = dst[e];
        int p = atomicAdd(&g_cursor[d], 1);
        int s = src[e];
        g_edge[p] = make_int2(s, __float_as_int(g_nsrc[s]));   // one 8B store
    }
}

// ---------------- fused layer: pull-agg (smem) + GEMM + bias + relu --------
// Block = 64 dst nodes, 256 threads, 2 CTAs/SM.
// Phase 1: warp w aggregates nodes w*8..w*8+7. Edge pairs are staged into a
//          per-warp smem buffer with ONE coalesced LDG (lane i -> edge i),
//          then read back via LDS broadcast -> feature LDG.128s are
//          independent and pipeline (no LDG->LDG dependent chain).
// Phase 2: 64x128 GEMM from smem, 2x8 f32x2 register tile per thread.
__global__ void __launch_bounds__(256, 2)
k_layer(const float* __restrict__ X, const float* __restrict__ W,
        const float* __restrict__ b, float* __restrict__ Y, int nrows) {
    extern __shared__ float smem[];
    float* Wsm = smem;             // [128][128]
    float* Asm = smem + D * D;     // [128][AST] transposed agg tile
    __shared__ int2 ebuf[8][32];   // per-warp edge staging
    int tid  = threadIdx.x;
    int w    = tid >> 5;
    int lane = tid & 31;
    int row0 = blockIdx.x * TM;

    // stage W (64 KB) — independent of agg, overlaps with it
    {
        const float4* W4   = (const float4*)W;
        float4*       Wsm4 = (float4*)Wsm;
#pragma unroll
        for (int i = 0; i < D * D / 4 / 256; i++)
            Wsm4[tid + i * 256] = W4[tid + i * 256];
    }

    // Phase 1: aggregation, 8 nodes per warp
#pragma unroll
    for (int n = 0; n < 8; n++) {
        int r = w * 8 + n;
        int v = row0 + r;
        float4 acc = make_float4(0.f, 0.f, 0.f, 0.f);
        if (v < nrows) {
            int beg = g_rowstart[v];
            int deg = g_indeg[v];
            for (int base = 0; base < deg; base += 32) {
                int m = min(32, deg - base);
                if (lane < m) ebuf[w][lane] = g_edge[beg + base + lane];
                __syncwarp();
                int e = 0;
                for (; e + 4 <= m; e += 4) {
                    int2 p0 = ebuf[w][e + 0];
                    int2 p1 = ebuf[w][e + 1];
                    int2 p2 = ebuf[w][e + 2];
                    int2 p3 = ebuf[w][e + 3];
                    float4 x0 = ((const float4*)(X + (size_t)p0.x * D))[lane];
                    float4 x1 = ((const float4*)(X + (size_t)p1.x * D))[lane];
                    float4 x2 = ((const float4*)(X + (size_t)p2.x * D))[lane];
                    float4 x3 = ((const float4*)(X + (size_t)p3.x * D))[lane];
                    float w0 = __int_as_float(p0.y), w1 = __int_as_float(p1.y);
                    float w2 = __int_as_float(p2.y), w3 = __int_as_float(p3.y);
                    acc.x = fmaf(x0.x, w0, acc.x); acc.y = fmaf(x0.y, w0, acc.y);
                    acc.z = fmaf(x0.z, w0, acc.z); acc.w = fmaf(x0.w, w0, acc.w);
                    acc.x = fmaf(x1.x, w1, acc.x); acc.y = fmaf(x1.y, w1, acc.y);
                    acc.z = fmaf(x1.z, w1, acc.z); acc.w = fmaf(x1.w, w1, acc.w);
                    acc.x = fmaf(x2.x, w2, acc.x); acc.y = fmaf(x2.y, w2, acc.y);
                    acc.z = fmaf(x2.z, w2, acc.z); acc.w = fmaf(x2.w, w2, acc.w);
                    acc.x = fmaf(x3.x, w3, acc.x); acc.y = fmaf(x3.y, w3, acc.y);
                    acc.z = fmaf(x3.z, w3, acc.z); acc.w = fmaf(x3.w, w3, acc.w);
                }
                for (; e < m; e++) {
                    int2 p0 = ebuf[w][e];
                    float w0 = __int_as_float(p0.y);
                    float4 x0 = ((const float4*)(X + (size_t)p0.x * D))[lane];
                    acc.x = fmaf(x0.x, w0, acc.x); acc.y = fmaf(x0.y, w0, acc.y);
                    acc.z = fmaf(x0.z, w0, acc.z); acc.w = fmaf(x0.w, w0, acc.w);
                }
                __syncwarp();
            }
            float nd = g_ndst[v];
            acc.x *= nd; acc.y *= nd; acc.z *= nd; acc.w *= nd;
        }
        // transposed store (pre-scaled); zeros for invalid rows
        float* ap = Asm + r;
        ap[(4 * lane + 0) * AST] = acc.x;
        ap[(4 * lane + 1) * AST] = acc.y;
        ap[(4 * lane + 2) * AST] = acc.z;
        ap[(4 * lane + 3) * AST] = acc.w;
    }
    __syncthreads();

    // Phase 2: GEMM 64x128, thread = 4 rows x 8 cols
    int tx = tid & 15;     // col group
    int ty = tid >> 4;     // row group
    int j0 = tx * 8;
    int r0 = ty * 4;

    unsigned long long acc[2][8];
#pragma unroll
    for (int p = 0; p < 2; p++)
#pragma unroll
        for (int c = 0; c < 8; c++) acc[p][c] = 0ULL;

#pragma unroll 4
    for (int k = 0; k < D; k++) {
        const unsigned long long* ap =
            (const unsigned long long*)(Asm + k * AST + r0);
        unsigned long long a0 = ap[0], a1 = ap[1];
        const float* wr = Wsm + k * D + j0;
        float4 wa = *(const float4*)(wr);
        float4 wb = *(const float4*)(wr + 4);
        unsigned long long wd[8];
        wd[0] = pack2(wa.x, wa.x); wd[1] = pack2(wa.y, wa.y);
        wd[2] = pack2(wa.z, wa.z); wd[3] = pack2(wa.w, wa.w);
        wd[4] = pack2(wb.x, wb.x); wd[5] = pack2(wb.y, wb.y);
        wd[6] = pack2(wb.z, wb.z); wd[7] = pack2(wb.w, wb.w);
#pragma unroll
        for (int c = 0; c < 8; c++) {
            fma2(acc[0][c], a0, wd[c]);
            fma2(acc[1][c], a1, wd[c]);
        }
    }

    float4 bva = *(const float4*)(b + j0);
    float4 bvb = *(const float4*)(b + j0 + 4);
    float bj[8] = {bva.x, bva.y, bva.z, bva.w, bvb.x, bvb.y, bvb.z, bvb.w};

#pragma unroll
    for (int p = 0; p < 2; p++) {
        float lo[8], hi[8];
#pragma unroll
        for (int c = 0; c < 8; c++) unpack2(acc[p][c], lo[c], hi[c]);
        int rA = row0 + r0 + 2 * p;
        int rB = rA + 1;
        if (rA < nrows) {
            float4 v0 = make_float4(fmaxf(lo[0]+bj[0],0.f), fmaxf(lo[1]+bj[1],0.f),
                                    fmaxf(lo[2]+bj[2],0.f), fmaxf(lo[3]+bj[3],0.f));
            float4 v1 = make_float4(fmaxf(lo[4]+bj[4],0.f), fmaxf(lo[5]+bj[5],0.f),
                                    fmaxf(lo[6]+bj[6],0.f), fmaxf(lo[7]+bj[7],0.f));
            *(float4*)(Y + rA * D + j0)     = v0;
            *(float4*)(Y + rA * D + j0 + 4) = v1;
        }
        if (rB < nrows) {
            float4 v0 = make_float4(fmaxf(hi[0]+bj[0],0.f), fmaxf(hi[1]+bj[1],0.f),
                                    fmaxf(hi[2]+bj[2],0.f), fmaxf(hi[3]+bj[3],0.f));
            float4 v1 = make_float4(fmaxf(hi[4]+bj[4],0.f), fmaxf(hi[5]+bj[5],0.f),
                                    fmaxf(hi[6]+bj[6],0.f), fmaxf(hi[7]+bj[7],0.f));
            *(float4*)(Y + rB * D + j0)     = v0;
            *(float4*)(Y + rB * D + j0 + 4) = v1;
        }
    }
}

// ------- readout (run-length, sorted gids) + fused head in last block -------
__global__ void k_readout(const float* __restrict__ X, const int* __restrict__ gid,
                          const float* __restrict__ Wm, const float* __restrict__ bm,
                          float* __restrict__ out) {
    __shared__ int sg[RCHUNK];
    int v0  = blockIdx.x * RCHUNK;
    int tid = threadIdx.x;                // 128
    int nv  = min(RCHUNK, N_NODES - v0);
    for (int i = tid; i < nv; i += 128) sg[i] = gid[v0 + i];
    __syncthreads();
    float acc = 0.0f;
    int cur = sg[0], run = 0;
    for (int i = 0; i < nv; i++) {
        int g = sg[i];
        if (g != cur) {
            atomicAdd(&g_hg[cur * D + tid], acc);
            if (tid == 0) atomicAdd(&g_cnt[cur], run);
            acc = 0.0f; run = 0; cur = g;
        }
        acc += X[(v0 + i) * D + tid];
        run++;
    }
    atomicAdd(&g_hg[cur * D + tid], acc);
    if (tid == 0) atomicAdd(&g_cnt[cur], run);

    // ---- last block performs the head (mean -> logits -> log_softmax axis 0)
    __threadfence();
    __shared__ int isLast;
    if (tid == 0) isLast = (atomicAdd(&g_ticket, 1) == (int)gridDim.x - 1);
    __syncthreads();
    if (!isLast) return;

    __shared__ float slog[N_GRAPHS * D_OUT];
    __shared__ float lse[D_OUT];
    for (int i = tid; i < N_GRAPHS * D_OUT; i += 128) {
        int g = i / D_OUT, j = i % D_OUT;
        float inv = 1.0f / (float)max(g_cnt[g], 1);
        float s = bm[j];
        for (int k = 0; k < D; k++) s += g_hg[g * D + k] * inv * Wm[k * D_OUT + j];
        slog[i] = s;
    }
    __syncthreads();
    if (tid < D_OUT) {
        float mx = -1e30f;
        for (int g = 0; g < N_GRAPHS; g++) mx = fmaxf(mx, slog[g * D_OUT + tid]);
        float s = 0.0f;
        for (int g = 0; g < N_GRAPHS; g++) s += expf(slog[g * D_OUT + tid] - mx);
        lse[tid] = mx + logf(s);
    }
    __syncthreads();
    for (int i = tid; i < N_GRAPHS * D_OUT; i += 128)
        out[i] = slog[i] - lse[i % D_OUT];
}

// ---------------- launcher ----------------
extern "C" void kernel_launch(void* const* d_in, const int* in_sizes, int n_in,
                              void* d_out, int out_size) {
    const float* h   = (const float*)d_in[0];
    const int*   src = (const int*)  d_in[1];
    const int*   dst = (const int*)  d_in[2];
    const int*   gid = (const int*)  d_in[3];
    const float* W1  = (const float*)d_in[4];
    const float* b1  = (const float*)d_in[5];
    const float* W2  = (const float*)d_in[6];
    const float* b2  = (const float*)d_in[7];
    const float* W3  = (const float*)d_in[8];
    const float* b3  = (const float*)d_in[9];
    const float* Wm  = (const float*)d_in[10];
    const float* bm  = (const float*)d_in[11];
    float*       out = (float*)d_out;

    const int smem_layer = (D * D + D * AST) * (int)sizeof(float);  // ~97 KB
    cudaFuncSetAttribute(k_layer, cudaFuncAttributeMaxDynamicSharedMemorySize, smem_layer);

    float *xa, *xb;
    cudaGetSymbolAddress((void**)&xa, g_xa);
    cudaGetSymbolAddress((void**)&xb, g_xb);

    int nb = (N_NODES + SCAN_B - 1) / SCAN_B;   // 49

    k_init<<<(N_NODES + 255) / 256, 256>>>();
    k_deg <<<(N_EDGES + 255) / 256, 256>>>(src, dst);
    kscan <<<nb, SCAN_B>>>();
    k_fill<<<(N_EDGES + 255) / 256, 256>>>(src, dst);

    int grid = (N_NODES + TM - 1) / TM;   // 782

    k_layer<<<grid, 256, smem_layer>>>(h,  W1, b1, xa, N_NODES);
    k_layer<<<grid, 256, smem_layer>>>(xa, W2, b2, xb, N_NODES);
    k_layer<<<grid, 256, smem_layer>>>(xb, W3, b3, xa, N_NODES);

    k_readout<<<(N_NODES + RCHUNK - 1) / RCHUNK, 128>>>(xa, gid, Wm, bm, out);
}

// round 10
// speedup vs baseline: 1.2016x; 1.2016x over previous
#include <cuda_runtime.h>
#include <math.h>

#define N_NODES  50000
#define N_EDGES  800000
#define N_GRAPHS 50
#define D        128
#define D_OUT    10

#define SCAN_B   1024
#define RCHUNK   256

#define TM  64             // fused-layer row tile
#define AST 66             // padded Asm row stride (even -> 8B-aligned pairs)

// ---------------- scratch (device globals: allocation-free) ----------------
__device__ int   g_indeg[N_NODES];
__device__ int   g_outdeg[N_NODES];
__device__ float g_nsrc[N_NODES];
__device__ float g_ndst[N_NODES];
__device__ int   g_rowstart[N_NODES];
__device__ int   g_cursor[N_NODES];
__device__ int2  g_edge[N_EDGES];        // (src_col, bitcast(norm_src))
__device__ int   g_blksums[64];
__device__ int   g_blkoff[64];
__device__ float g_xa [N_NODES * D];
__device__ float g_xb [N_NODES * D];
__device__ float g_hg [N_GRAPHS * D];
__device__ int   g_cnt[N_GRAPHS];

// ---------------- packed f32x2 helpers (sm_100+) ----------------
__device__ __forceinline__ unsigned long long pack2(float lo, float hi) {
    unsigned long long r;
    asm("mov.b64 %0, {%1, %2};" : "=l"(r) : "f"(lo), "f"(hi));
    return r;
}
__device__ __forceinline__ void unpack2(unsigned long long v, float &lo, float &hi) {
    asm("mov.b64 {%0, %1}, %2;" : "=f"(lo), "=f"(hi) : "l"(v));
}
__device__ __forceinline__ void fma2(unsigned long long &acc,
                                     unsigned long long a, unsigned long long b) {
    asm("fma.rn.f32x2 %0, %1, %2, %0;" : "+l"(acc) : "l"(a), "l"(b));
}
__device__ __forceinline__ void fma4(float4 &acc, float4 x, float s) {
    acc.x = fmaf(x.x, s, acc.x); acc.y = fmaf(x.y, s, acc.y);
    acc.z = fmaf(x.z, s, acc.z); acc.w = fmaf(x.w, s, acc.w);
}

// ---------------- setup kernels ----------------
__global__ void k_init() {
    int i = blockIdx.x * blockDim.x + threadIdx.x;
    if (i < N_NODES) { g_indeg[i] = 0; g_outdeg[i] = 0; }
}

__global__ void k_deg(const int* __restrict__ src, const int* __restrict__ dst) {
    int e = blockIdx.x * blockDim.x + threadIdx.x;
    if (e < N_EDGES) {
        atomicAdd(&g_outdeg[src[e]], 1);
        atomicAdd(&g_indeg[dst[e]], 1);
    }
}

// two-level exclusive scan of g_indeg -> g_rowstart
__global__ void kscan1() {
    __shared__ int sm[SCAN_B];
    int i = blockIdx.x * SCAN_B + threadIdx.x;
    int v = (i < N_NODES) ? g_indeg[i] : 0;
    sm[threadIdx.x] = v;
    __syncthreads();
    for (int off = 1; off < SCAN_B; off <<= 1) {
        int t = (threadIdx.x >= off) ? sm[threadIdx.x - off] : 0;
        __syncthreads();
        sm[threadIdx.x] += t;
        __syncthreads();
    }
    if (i < N_NODES) g_rowstart[i] = sm[threadIdx.x] - v;       // exclusive (local)
    if (threadIdx.x == SCAN_B - 1) g_blksums[blockIdx.x] = sm[SCAN_B - 1];
}

__global__ void kscan2(int nb) {
    __shared__ int s[64];
    int tid = threadIdx.x;            // 64 threads
    int v = (tid < nb) ? g_blksums[tid] : 0;
    s[tid] = v;
    __syncthreads();
    for (int off = 1; off < 64; off <<= 1) {
        int t = (tid >= off) ? s[tid - off] : 0;
        __syncthreads();
        s[tid] += t;
        __syncthreads();
    }
    if (tid < nb) g_blkoff[tid] = s[tid] - v;   // exclusive
}

// scan finalize + norms + zero readout accumulators (fused)
__global__ void kscan3() {
    int i = blockIdx.x * SCAN_B + threadIdx.x;
    if (i < N_NODES) {
        int rs = g_rowstart[i] + g_blkoff[blockIdx.x];
        g_rowstart[i] = rs;
        g_cursor[i]   = rs;
        g_nsrc[i] = rsqrtf((float)max(g_outdeg[i], 1));
        g_ndst[i] = rsqrtf((float)max(g_indeg[i], 1));
    }
    if (i < N_GRAPHS * D) g_hg[i] = 0.0f;
    if (i < N_GRAPHS) g_cnt[i] = 0;
}

__global__ void k_fill(const int* __restrict__ src, const int* __restrict__ dst) {
    int e = blockIdx.x * blockDim.x + threadIdx.x;
    if (e < N_EDGES) {
        int d = dst[e];
        int p = atomicAdd(&g_cursor[d], 1);
        int s = src[e];
        g_edge[p] = make_int2(s, __float_as_int(g_nsrc[s]));   // one 8B store
    }
}

// ---------------- fused layer: pull-agg (regs) + GEMM + bias + relu --------
// Block = 64 dst nodes, 256 threads, 2 CTAs/SM.
// Phase 1: warp w aggregates nodes w*8..w*8+7 as INTERLEAVED PAIRS — two
//          independent accumulator chains double the LDGs in flight
//          (8 edge LDG.64 + 8 feature LDG.128) with zero sync overhead.
// Phase 2: 64x128 GEMM from smem, 2x8 f32x2 register tile per thread.
__global__ void __launch_bounds__(256, 2)
k_layer(const float* __restrict__ X, const float* __restrict__ W,
        const float* __restrict__ b, float* __restrict__ Y, int nrows) {
    extern __shared__ float smem[];
    float* Wsm = smem;             // [128][128]
    float* Asm = smem + D * D;     // [128][AST] transposed agg tile
    int tid  = threadIdx.x;
    int w    = tid >> 5;
    int lane = tid & 31;
    int row0 = blockIdx.x * TM;

    // stage W (64 KB) — independent of agg, overlaps with it
    {
        const float4* W4   = (const float4*)W;
        float4*       Wsm4 = (float4*)Wsm;
#pragma unroll
        for (int i = 0; i < D * D / 4 / 256; i++)
            Wsm4[tid + i * 256] = W4[tid + i * 256];
    }

    // Phase 1: aggregation, 8 nodes per warp, processed as 4 pairs
#pragma unroll
    for (int n = 0; n < 8; n += 2) {
        int rA = w * 8 + n;
        int vA = row0 + rA;
        int vB = vA + 1;
        int begA = 0, degA = 0, begB = 0, degB = 0;
        if (vA < nrows) { begA = g_rowstart[vA]; degA = g_indeg[vA]; }
        if (vB < nrows) { begB = g_rowstart[vB]; degB = g_indeg[vB]; }
        float4 accA = make_float4(0.f, 0.f, 0.f, 0.f);
        float4 accB = make_float4(0.f, 0.f, 0.f, 0.f);

        int mn = min(degA, degB);
        int e = 0;
        // interleaved main loop: 2 edges per node per iter, two indep chains
        for (; e + 2 <= mn; e += 2) {
            int2 a0 = g_edge[begA + e], a1 = g_edge[begA + e + 1];
            int2 b0 = g_edge[begB + e], b1 = g_edge[begB + e + 1];
            float4 xa0 = ((const float4*)(X + (size_t)a0.x * D))[lane];
            float4 xb0 = ((const float4*)(X + (size_t)b0.x * D))[lane];
            float4 xa1 = ((const float4*)(X + (size_t)a1.x * D))[lane];
            float4 xb1 = ((const float4*)(X + (size_t)b1.x * D))[lane];
            fma4(accA, xa0, __int_as_float(a0.y));
            fma4(accB, xb0, __int_as_float(b0.y));
            fma4(accA, xa1, __int_as_float(a1.y));
            fma4(accB, xb1, __int_as_float(b1.y));
        }
        // A tail (4-edge unroll, then scalar)
        int eA = e;
        for (; eA + 4 <= degA; eA += 4) {
            int2 p0 = g_edge[begA + eA + 0];
            int2 p1 = g_edge[begA + eA + 1];
            int2 p2 = g_edge[begA + eA + 2];
            int2 p3 = g_edge[begA + eA + 3];
            float4 x0 = ((const float4*)(X + (size_t)p0.x * D))[lane];
            float4 x1 = ((const float4*)(X + (size_t)p1.x * D))[lane];
            float4 x2 = ((const float4*)(X + (size_t)p2.x * D))[lane];
            float4 x3 = ((const float4*)(X + (size_t)p3.x * D))[lane];
            fma4(accA, x0, __int_as_float(p0.y));
            fma4(accA, x1, __int_as_float(p1.y));
            fma4(accA, x2, __int_as_float(p2.y));
            fma4(accA, x3, __int_as_float(p3.y));
        }
        for (; eA < degA; eA++) {
            int2 p0 = g_edge[begA + eA];
            float4 x0 = ((const float4*)(X + (size_t)p0.x * D))[lane];
            fma4(accA, x0, __int_as_float(p0.y));
        }
        // B tail
        int eB = e;
        for (; eB + 4 <= degB; eB += 4) {
            int2 p0 = g_edge[begB + eB + 0];
            int2 p1 = g_edge[begB + eB + 1];
            int2 p2 = g_edge[begB + eB + 2];
            int2 p3 = g_edge[begB + eB + 3];
            float4 x0 = ((const float4*)(X + (size_t)p0.x * D))[lane];
            float4 x1 = ((const float4*)(X + (size_t)p1.x * D))[lane];
            float4 x2 = ((const float4*)(X + (size_t)p2.x * D))[lane];
            float4 x3 = ((const float4*)(X + (size_t)p3.x * D))[lane];
            fma4(accB, x0, __int_as_float(p0.y));
            fma4(accB, x1, __int_as_float(p1.y));
            fma4(accB, x2, __int_as_float(p2.y));
            fma4(accB, x3, __int_as_float(p3.y));
        }
        for (; eB < degB; eB++) {
            int2 p0 = g_edge[begB + eB];
            float4 x0 = ((const float4*)(X + (size_t)p0.x * D))[lane];
            fma4(accB, x0, __int_as_float(p0.y));
        }

        if (vA < nrows) {
            float nd = g_ndst[vA];
            accA.x *= nd; accA.y *= nd; accA.z *= nd; accA.w *= nd;
        }
        if (vB < nrows) {
            float nd = g_ndst[vB];
            accB.x *= nd; accB.y *= nd; accB.z *= nd; accB.w *= nd;
        }
        // transposed stores (pre-scaled); zeros for invalid rows
        float* apA = Asm + rA;
        float* apB = Asm + rA + 1;
        apA[(4 * lane + 0) * AST] = accA.x;  apB[(4 * lane + 0) * AST] = accB.x;
        apA[(4 * lane + 1) * AST] = accA.y;  apB[(4 * lane + 1) * AST] = accB.y;
        apA[(4 * lane + 2) * AST] = accA.z;  apB[(4 * lane + 2) * AST] = accB.z;
        apA[(4 * lane + 3) * AST] = accA.w;  apB[(4 * lane + 3) * AST] = accB.w;
    }
    __syncthreads();

    // Phase 2: GEMM 64x128, thread = 4 rows x 8 cols
    int tx = tid & 15;     // col group
    int ty = tid >> 4;     // row group
    int j0 = tx * 8;
    int r0 = ty * 4;

    unsigned long long acc[2][8];
#pragma unroll
    for (int p = 0; p < 2; p++)
#pragma unroll
        for (int c = 0; c < 8; c++) acc[p][c] = 0ULL;

#pragma unroll 4
    for (int k = 0; k < D; k++) {
        const unsigned long long* ap =
            (const unsigned long long*)(Asm + k * AST + r0);
        unsigned long long a0 = ap[0], a1 = ap[1];
        const float* wr = Wsm + k * D + j0;
        float4 wa = *(const float4*)(wr);
        float4 wb = *(const float4*)(wr + 4);
        unsigned long long wd[8];
        wd[0] = pack2(wa.x, wa.x); wd[1] = pack2(wa.y, wa.y);
        wd[2] = pack2(wa.z, wa.z); wd[3] = pack2(wa.w, wa.w);
        wd[4] = pack2(wb.x, wb.x); wd[5] = pack2(wb.y, wb.y);
        wd[6] = pack2(wb.z, wb.z); wd[7] = pack2(wb.w, wb.w);
#pragma unroll
        for (int c = 0; c < 8; c++) {
            fma2(acc[0][c], a0, wd[c]);
            fma2(acc[1][c], a1, wd[c]);
        }
    }

    float4 bva = *(const float4*)(b + j0);
    float4 bvb = *(const float4*)(b + j0 + 4);
    float bj[8] = {bva.x, bva.y, bva.z, bva.w, bvb.x, bvb.y, bvb.z, bvb.w};

#pragma unroll
    for (int p = 0; p < 2; p++) {
        float lo[8], hi[8];
#pragma unroll
        for (int c = 0; c < 8; c++) unpack2(acc[p][c], lo[c], hi[c]);
        int rA = row0 + r0 + 2 * p;
        int rB = rA + 1;
        if (rA < nrows) {
            float4 v0 = make_float4(fmaxf(lo[0]+bj[0],0.f), fmaxf(lo[1]+bj[1],0.f),
                                    fmaxf(lo[2]+bj[2],0.f), fmaxf(lo[3]+bj[3],0.f));
            float4 v1 = make_float4(fmaxf(lo[4]+bj[4],0.f), fmaxf(lo[5]+bj[5],0.f),
                                    fmaxf(lo[6]+bj[6],0.f), fmaxf(lo[7]+bj[7],0.f));
            *(float4*)(Y + rA * D + j0)     = v0;
            *(float4*)(Y + rA * D + j0 + 4) = v1;
        }
        if (rB < nrows) {
            float4 v0 = make_float4(fmaxf(hi[0]+bj[0],0.f), fmaxf(hi[1]+bj[1],0.f),
                                    fmaxf(hi[2]+bj[2],0.f), fmaxf(hi[3]+bj[3],0.f));
            float4 v1 = make_float4(fmaxf(hi[4]+bj[4],0.f), fmaxf(hi[5]+bj[5],0.f),
                                    fmaxf(hi[6]+bj[6],0.f), fmaxf(hi[7]+bj[7],0.f));
            *(float4*)(Y + rB * D + j0)     = v0;
            *(float4*)(Y + rB * D + j0 + 4) = v1;
        }
    }
}

// ---------------- readout: sorted graph_ids -> run-length + rare atomics ----
__global__ void k_readout(const float* __restrict__ X, const int* __restrict__ gid) {
    __shared__ int sg[RCHUNK];
    int v0  = blockIdx.x * RCHUNK;
    int tid = threadIdx.x;                // 128
    int nv  = min(RCHUNK, N_NODES - v0);
    for (int i = tid; i < nv; i += 128) sg[i] = gid[v0 + i];
    __syncthreads();
    float acc = 0.0f;
    int cur = sg[0], run = 0;
    for (int i = 0; i < nv; i++) {
        int g = sg[i];
        if (g != cur) {
            atomicAdd(&g_hg[cur * D + tid], acc);
            if (tid == 0) atomicAdd(&g_cnt[cur], run);
            acc = 0.0f; run = 0; cur = g;
        }
        acc += X[(v0 + i) * D + tid];
        run++;
    }
    atomicAdd(&g_hg[cur * D + tid], acc);
    if (tid == 0) atomicAdd(&g_cnt[cur], run);
}

// ---------------- head: mean -> logits -> log_softmax over axis 0 ----------
__global__ void k_head(const float* __restrict__ Wm, const float* __restrict__ bm,
                       float* __restrict__ out) {
    __shared__ float slog[N_GRAPHS * D_OUT];
    __shared__ float lse[D_OUT];
    int tid = threadIdx.x;   // 512
    if (tid < N_GRAPHS * D_OUT) {
        int g = tid / D_OUT, j = tid % D_OUT;
        float inv = 1.0f / (float)max(g_cnt[g], 1);
        float s = bm[j];
        for (int k = 0; k < D; k++) s += g_hg[g * D + k] * inv * Wm[k * D_OUT + j];
        slog[tid] = s;
    }
    __syncthreads();
    if (tid < D_OUT) {
        float mx = -1e30f;
        for (int g = 0; g < N_GRAPHS; g++) mx = fmaxf(mx, slog[g * D_OUT + tid]);
        float s = 0.0f;
        for (int g = 0; g < N_GRAPHS; g++) s += expf(slog[g * D_OUT + tid] - mx);
        lse[tid] = mx + logf(s);
    }
    __syncthreads();
    if (tid < N_GRAPHS * D_OUT) {
        int j = tid % D_OUT;
        out[tid] = slog[tid] - lse[j];
    }
}

// ---------------- launcher ----------------
extern "C" void kernel_launch(void* const* d_in, const int* in_sizes, int n_in,
                              void* d_out, int out_size) {
    const float* h   = (const float*)d_in[0];
    const int*   src = (const int*)  d_in[1];
    const int*   dst = (const int*)  d_in[2];
    const int*   gid = (const int*)  d_in[3];
    const float* W1  = (const float*)d_in[4];
    const float* b1  = (const float*)d_in[5];
    const float* W2  = (const float*)d_in[6];
    const float* b2  = (const float*)d_in[7];
    const float* W3  = (const float*)d_in[8];
    const float* b3  = (const float*)d_in[9];
    const float* Wm  = (const float*)d_in[10];
    const float* bm  = (const float*)d_in[11];
    float*       out = (float*)d_out;

    const int smem_layer = (D * D + D * AST) * (int)sizeof(float);  // ~97 KB
    cudaFuncSetAttribute(k_layer, cudaFuncAttributeMaxDynamicSharedMemorySize, smem_layer);

    float *xa, *xb;
    cudaGetSymbolAddress((void**)&xa, g_xa);
    cudaGetSymbolAddress((void**)&xb, g_xb);

    int nb = (N_NODES + SCAN_B - 1) / SCAN_B;

    k_init<<<(N_NODES + 255) / 256, 256>>>();
    k_deg <<<(N_EDGES + 255) / 256, 256>>>(src, dst);
    kscan1<<<nb, SCAN_B>>>();
    kscan2<<<1, 64>>>(nb);
    kscan3<<<nb, SCAN_B>>>();
    k_fill<<<(N_EDGES + 255) / 256, 256>>>(src, dst);

    int grid = (N_NODES + TM - 1) / TM;   // 782

    k_layer<<<grid, 256, smem_layer>>>(h,  W1, b1, xa, N_NODES);
    k_layer<<<grid, 256, smem_layer>>>(xa, W2, b2, xb, N_NODES);
    k_layer<<<grid, 256, smem_layer>>>(xb, W3, b3, xa, N_NODES);

    k_readout<<<(N_NODES + RCHUNK - 1) / RCHUNK, 128>>>(xa, gid);
    k_head<<<1, 512>>>(Wm, bm, out);
}